// round 8
// baseline (speedup 1.0000x reference)
#include <cuda_runtime.h>
#include <cstdint>
#include <math.h>

// Problem constants
#define T_    4
#define B_    32
#define N_    512
#define D_    256
#define H_    4
#define M_TOT (T_*B_*N_)          // 65536 rows
#define TPLANE (B_*N_*D_)         // 4194304 elements per timestep plane
#define PLANE (T_*TPLANE)         // 16777216 elements per full (T,B,N,D) tensor
#define BN_   (B_*N_)             // 16384
#define MASK_PER (T_*B_*N_*H_*2)  // 524288 uint32 words per spike tensor
#define FULLM 0xffffffffu

// ---------------------------------------------------------------------------
// Scratch (device globals; no cudaMalloc allowed)
// ---------------------------------------------------------------------------
__device__ float        g_y[3][PLANE];        // pre-activation q/k/v (192 MiB)
__device__ unsigned int g_masks[3][MASK_PER]; // q/k/v spike bitmasks (6 MiB)
__device__ float        g_attn[PLANE];        // attention output (t,b,n,D)
__device__ float        g_proj[PLANE];        // after wo projection

// ---------------------------------------------------------------------------
// SGEMM (NT): C[M,256] = A[M,256] * W[256,256]^T, fp32.
// Pure ascending-k serial FMA per output element == cuBLAS SGEMM rounding.
// BM=BN=128, BK=16, 256 threads, 8x8 register tile.
// ---------------------------------------------------------------------------
__global__ __launch_bounds__(256) void sgemm_nt(const float* __restrict__ A,
                                                const float* __restrict__ W,
                                                float* __restrict__ C) {
    __shared__ float As[16][132];
    __shared__ float Ws[16][132];
    const int tid  = threadIdx.x;
    const int bm   = blockIdx.x * 128;
    const int bn   = blockIdx.y * 128;
    const int trow = (tid >> 4) * 8;
    const int tcol = (tid & 15) * 8;

    float acc[8][8];
#pragma unroll
    for (int i = 0; i < 8; i++)
#pragma unroll
        for (int j = 0; j < 8; j++) acc[i][j] = 0.f;

    const int lrow = tid >> 2;        // 0..63
    const int lkc  = (tid & 3) * 4;   // 0,4,8,12

    for (int k0 = 0; k0 < 256; k0 += 16) {
#pragma unroll
        for (int l = 0; l < 2; l++) {
            int row = lrow + l * 64;
            float4 av = *reinterpret_cast<const float4*>(&A[(size_t)(bm + row) * 256 + k0 + lkc]);
            float4 wv = *reinterpret_cast<const float4*>(&W[(size_t)(bn + row) * 256 + k0 + lkc]);
            As[lkc + 0][row] = av.x; As[lkc + 1][row] = av.y;
            As[lkc + 2][row] = av.z; As[lkc + 3][row] = av.w;
            Ws[lkc + 0][row] = wv.x; Ws[lkc + 1][row] = wv.y;
            Ws[lkc + 2][row] = wv.z; Ws[lkc + 3][row] = wv.w;
        }
        __syncthreads();
#pragma unroll
        for (int kk = 0; kk < 16; kk++) {
            float a[8], b[8];
#pragma unroll
            for (int i = 0; i < 8; i++) a[i] = As[kk][trow + i];
#pragma unroll
            for (int j = 0; j < 8; j++) b[j] = Ws[kk][tcol + j];
#pragma unroll
            for (int i = 0; i < 8; i++)
#pragma unroll
                for (int j = 0; j < 8; j++) acc[i][j] = fmaf(a[i], b[j], acc[i][j]);
        }
        __syncthreads();
    }
#pragma unroll
    for (int i = 0; i < 8; i++) {
        float* cp = &C[(size_t)(bm + trow + i) * 256 + bn + tcol];
#pragma unroll
        for (int j = 0; j < 8; j++) cp[j] = acc[i][j];
    }
}

// ---------------------------------------------------------------------------
// PLIF over T for q/k/v pre-activations -> spike bitmasks.
// decay = sigmoid(0) = exactly 0.5, so (x-v)*decay is EXACT; h has a single
// add rounding -> platform-independent. spike = (h >= 1).
// Mask layout: [((t*BN + bn)*H + h)*2 + word], word = (d>>5)&1, h = d>>6.
// ---------------------------------------------------------------------------
__global__ __launch_bounds__(256) void plif_spikes(const float* __restrict__ y,
                                                   const float* __restrict__ wp,
                                                   unsigned int* __restrict__ masks) {
    const int bn   = blockIdx.x;
    const int d    = threadIdx.x;
    const int lane = d & 31;
    const float decay = 1.f / (1.f + expf(-wp[0]));   // w=0 -> exactly 0.5
    const int idx0 = bn * 256 + d;
    float v = 0.f;
#pragma unroll
    for (int t = 0; t < 4; t++) {
        float u = y[(size_t)t * TPLANE + idx0];
        float h = __fadd_rn(v, __fmul_rn(__fsub_rn(u, v), decay));
        bool s = (h >= 1.0f);
        v = s ? 0.f : h;
        unsigned int bal = __ballot_sync(FULLM, s);
        if (lane == 0) {
            int hh   = d >> 6;
            int word = (d >> 5) & 1;
            masks[((t * BN_ + bn) * H_ + hh) * 2 + word] = bal;
        }
    }
}

// ---------------------------------------------------------------------------
// Fused attention per (t,b,h).
// Logits = popc(q&k)*0.125 (exact). exp args exact -> LUT[d] = expf(-0.125*d)
// (libdevice expf == XLA-GPU exp lowering, bitwise).
// Softmax denominator: XLA-GPU canonical 512-thread reduce association:
//   simulated warp j (elements 32j..32j+31) -> shfl.down tree (16,8,4,2,1),
//   then 16 warp partials combined by balanced tree ((p0+p8)+(p4+p12))+...
// w = fl(e/s); attn_out = fl(0.1*w) (attn PLIF provably never spikes:
// softmax < 1 = V_TH). AV = ascending sparse walk over v bits == cuBLAS
// serial-ascending FMA (v in {0,1}: fma(p,0,acc) is an exact no-op).
// Grid: x=(t*B+b)*H+h (512), y=row-block of 128 (4). 256 thr, warp per row.
// ---------------------------------------------------------------------------
__global__ __launch_bounds__(256) void attn_kernel(float* __restrict__ out) {
    const int tbh = blockIdx.x;
    const int h   = tbh & 3;
    const int tb  = tbh >> 2;              // t*32+b
    const int rowbase = blockIdx.y * 128;
    const int tid  = threadIdx.x;
    const int warp = tid >> 5;
    const int lane = tid & 31;

    __shared__ unsigned int klo[512], khi[512], vlo[512], vhi[512];
    __shared__ unsigned int vc[64][17];        // column-major v bits, padded
    __shared__ unsigned char dbuf[8][512];     // per-row (maxpc - pc) per m
    __shared__ float wtab[8][68];              // per-row 0.1*(LUT[d]/s)
    __shared__ float lut[65];                  // expf(-0.125*d)

    if (tid < 65) lut[tid] = expf(-0.125f * (float)tid);

    const unsigned int* qm = g_masks[0];
    const unsigned int* km = g_masks[1];
    const unsigned int* vm = g_masks[2];

    for (int n = tid; n < 512; n += 256) {
        int mi = ((tb * 512 + n) * 4 + h) * 2;
        klo[n] = km[mi]; khi[n] = km[mi + 1];
        vlo[n] = vm[mi]; vhi[n] = vm[mi + 1];
    }
    __syncthreads();

    // Transpose v bits into per-d columns via ballot
    for (int c = warp; c < 16; c += 8) {
        unsigned int wl = vlo[c * 32 + lane];
        unsigned int wh = vhi[c * 32 + lane];
#pragma unroll
        for (int dd = 0; dd < 32; dd++) {
            unsigned int b0 = __ballot_sync(FULLM, (wl >> dd) & 1u);
            unsigned int b1 = __ballot_sync(FULLM, (wh >> dd) & 1u);
            if (lane == dd) { vc[dd][c] = b0; vc[dd + 32][c] = b1; }
        }
    }
    __syncthreads();

    for (int it = 0; it < 16; it++) {
        int n  = rowbase + it * 8 + warp;
        int mi = ((tb * 512 + n) * 4 + h) * 2;
        unsigned int ql = qm[mi], qh = qm[mi + 1];

        // popcount logits (exact); row max (order-free on exact ints)
        int pc[16];
        int mx = 0;
#pragma unroll
        for (int j = 0; j < 16; j++) {
            int m = j * 32 + lane;
            pc[j] = __popc(ql & klo[m]) + __popc(qh & khi[m]);
            mx = max(mx, pc[j]);
        }
#pragma unroll
        for (int o = 16; o > 0; o >>= 1) mx = max(mx, __shfl_xor_sync(FULLM, mx, o));

        // exp values; per-simulated-warp shfl.down tree (XLA warp reduce)
        float p[16];
#pragma unroll
        for (int j = 0; j < 16; j++) {
            int dlt = mx - pc[j];
            dbuf[warp][j * 32 + lane] = (unsigned char)dlt;
            float v = lut[dlt];
            v = __fadd_rn(v, __shfl_down_sync(FULLM, v, 16));
            v = __fadd_rn(v, __shfl_down_sync(FULLM, v, 8));
            v = __fadd_rn(v, __shfl_down_sync(FULLM, v, 4));
            v = __fadd_rn(v, __shfl_down_sync(FULLM, v, 2));
            v = __fadd_rn(v, __shfl_down_sync(FULLM, v, 1));
            p[j] = __shfl_sync(FULLM, v, 0);   // warp-j partial, broadcast
        }
        // inter-warp combine: balanced down-tree over 16 partials (zero-padded
        // to 32 lanes in XLA -> offsets 16 add zeros exactly, then 8,4,2,1)
        float q0 = __fadd_rn(p[0], p[8]),  q1 = __fadd_rn(p[1], p[9]);
        float q2 = __fadd_rn(p[2], p[10]), q3 = __fadd_rn(p[3], p[11]);
        float q4 = __fadd_rn(p[4], p[12]), q5 = __fadd_rn(p[5], p[13]);
        float q6 = __fadd_rn(p[6], p[14]), q7 = __fadd_rn(p[7], p[15]);
        float r0 = __fadd_rn(q0, q4), r1 = __fadd_rn(q1, q5);
        float r2 = __fadd_rn(q2, q6), r3 = __fadd_rn(q3, q7);
        float s0 = __fadd_rn(r0, r2), s1 = __fadd_rn(r1, r3);
        float s  = __fadd_rn(s0, s1);

        // per-distinct-value attn_out = fl(0.1 * fl(e/s)) (reference order)
        for (int d = lane; d < 65; d += 32)
            wtab[warp][d] = __fmul_rn(0.1f, __fdiv_rn(lut[d], s));
        __syncwarp();

        // sparse attn @ v: ascending walk == serial ascending-m FMA
        float acc0 = 0.f, acc1 = 0.f;
        const int d0 = lane, d1 = lane + 32;
#pragma unroll 4
        for (int c = 0; c < 16; c++) {
            unsigned int w0 = vc[d0][c];
            unsigned int w1 = vc[d1][c];
            const unsigned char* db = &dbuf[warp][c * 32];
            while (w0) { int j = __ffs(w0) - 1; w0 &= w0 - 1; acc0 = __fadd_rn(acc0, wtab[warp][db[j]]); }
            while (w1) { int j = __ffs(w1) - 1; w1 &= w1 - 1; acc1 = __fadd_rn(acc1, wtab[warp][db[j]]); }
        }
        int ob = (tb * 512 + n) * 256 + h * 64;
        out[ob + d0] = acc0;
        out[ob + d1] = acc1;
        __syncwarp();
    }
}

// ---------------------------------------------------------------------------
// LayerNorm over D then final PLIF over T.
// Block = one (b,n) row, 256 threads, one element per thread (XLA-GPU
// canonical 256-thread row reduce): warp shfl.down tree -> 8 partials,
// zero-padded to 32 lanes, second shfl.down tree in warp 0.
// rs = rsqrtf(var+eps) (libdevice __nv_rsqrtf == lax.rsqrt lowering).
// gamma=*applied* but =1 (exact no-op); beta=0 (exact no-op). PLIF unfused
// (mul by 0.5 exact -> single-rounding h).
// ---------------------------------------------------------------------------
__global__ __launch_bounds__(256) void ln_plif(const float* __restrict__ X,
                                               const float* __restrict__ gamma,
                                               const float* __restrict__ beta,
                                               const float* __restrict__ wp,
                                               float* __restrict__ out) {
    const int bn   = blockIdx.x;
    const int d    = threadIdx.x;
    const int lane = d & 31, warp = d >> 5;
    __shared__ float part[8];
    __shared__ float bcast;
    const float decay = 1.f / (1.f + expf(-wp[0]));   // exactly 0.5
    const float g  = gamma[d];
    const float be = beta[d];
    float v = 0.f;

#pragma unroll
    for (int t = 0; t < 4; t++) {
        float x = X[(size_t)t * TPLANE + (size_t)bn * 256 + d];

        // ---- mean: warp down-tree, then padded down-tree over 8 partials ----
        float sv = x;
        sv = __fadd_rn(sv, __shfl_down_sync(FULLM, sv, 16));
        sv = __fadd_rn(sv, __shfl_down_sync(FULLM, sv, 8));
        sv = __fadd_rn(sv, __shfl_down_sync(FULLM, sv, 4));
        sv = __fadd_rn(sv, __shfl_down_sync(FULLM, sv, 2));
        sv = __fadd_rn(sv, __shfl_down_sync(FULLM, sv, 1));
        if (lane == 0) part[warp] = sv;
        __syncthreads();
        if (warp == 0) {
            float pv = (lane < 8) ? part[lane] : 0.f;
            pv = __fadd_rn(pv, __shfl_down_sync(FULLM, pv, 16));  // +0 exact
            pv = __fadd_rn(pv, __shfl_down_sync(FULLM, pv, 8));   // +0 exact
            pv = __fadd_rn(pv, __shfl_down_sync(FULLM, pv, 4));
            pv = __fadd_rn(pv, __shfl_down_sync(FULLM, pv, 2));
            pv = __fadd_rn(pv, __shfl_down_sync(FULLM, pv, 1));
            if (lane == 0) bcast = __fmul_rn(pv, (1.f / 256.f));  // exact pow2
        }
        __syncthreads();
        float mu = bcast;
        __syncthreads();

        // ---- variance: same association over centered squares ----
        float c  = __fsub_rn(x, mu);
        float qv = __fmul_rn(c, c);
        qv = __fadd_rn(qv, __shfl_down_sync(FULLM, qv, 16));
        qv = __fadd_rn(qv, __shfl_down_sync(FULLM, qv, 8));
        qv = __fadd_rn(qv, __shfl_down_sync(FULLM, qv, 4));
        qv = __fadd_rn(qv, __shfl_down_sync(FULLM, qv, 2));
        qv = __fadd_rn(qv, __shfl_down_sync(FULLM, qv, 1));
        if (lane == 0) part[warp] = qv;
        __syncthreads();
        if (warp == 0) {
            float pv = (lane < 8) ? part[lane] : 0.f;
            pv = __fadd_rn(pv, __shfl_down_sync(FULLM, pv, 16));
            pv = __fadd_rn(pv, __shfl_down_sync(FULLM, pv, 8));
            pv = __fadd_rn(pv, __shfl_down_sync(FULLM, pv, 4));
            pv = __fadd_rn(pv, __shfl_down_sync(FULLM, pv, 2));
            pv = __fadd_rn(pv, __shfl_down_sync(FULLM, pv, 1));
            if (lane == 0) bcast = __fmul_rn(pv, (1.f / 256.f));
        }
        __syncthreads();
        float var = bcast;
        __syncthreads();

        float rs = rsqrtf(__fadd_rn(var, 1e-5f));
        float y  = __fadd_rn(__fmul_rn(__fmul_rn(c, rs), g), be);
        float hh = __fadd_rn(v, __fmul_rn(__fsub_rn(y, v), decay));
        bool sp = (hh >= 1.0f);
        out[(size_t)t * TPLANE + (size_t)bn * 256 + d] = sp ? 1.f : 0.f;
        v = sp ? 0.f : hh;
    }
}

// ---------------------------------------------------------------------------
extern "C" void kernel_launch(void* const* d_in, const int* in_sizes, int n_in,
                              void* d_out, int out_size) {
    const float* x     = (const float*)d_in[0];
    const float* wq    = (const float*)d_in[1];
    const float* wk    = (const float*)d_in[2];
    const float* wv    = (const float*)d_in[3];
    const float* wo    = (const float*)d_in[4];
    const float* gamma = (const float*)d_in[5];
    const float* beta  = (const float*)d_in[6];
    const float* w_q   = (const float*)d_in[7];
    const float* w_k   = (const float*)d_in[8];
    const float* w_v   = (const float*)d_in[9];
    // d_in[10] = w_attn: unused — attn PLIF provably never spikes (softmax < V_TH)
    const float* w_p   = (const float*)d_in[11];

    float* y;  float* attn;  float* proj;  unsigned int* masks;
    cudaGetSymbolAddress((void**)&y,     g_y);
    cudaGetSymbolAddress((void**)&masks, g_masks);
    cudaGetSymbolAddress((void**)&attn,  g_attn);
    cudaGetSymbolAddress((void**)&proj,  g_proj);

    dim3 gg(M_TOT / 128, 2);

    // q/k/v pre-activation GEMMs
    sgemm_nt<<<gg, 256>>>(x, wq, y);
    sgemm_nt<<<gg, 256>>>(x, wk, y + (size_t)PLANE);
    sgemm_nt<<<gg, 256>>>(x, wv, y + (size_t)2 * PLANE);

    // PLIF -> spike bitmasks
    plif_spikes<<<BN_, 256>>>(y,                    w_q, masks);
    plif_spikes<<<BN_, 256>>>(y + (size_t)PLANE,    w_k, masks + MASK_PER);
    plif_spikes<<<BN_, 256>>>(y + (size_t)2*PLANE,  w_v, masks + 2 * MASK_PER);

    // fused attention (popcount logits + XLA-tree softmax + sparse AV)
    attn_kernel<<<dim3(T_ * B_ * H_, 4), 256>>>(attn);

    // output projection
    sgemm_nt<<<gg, 256>>>(attn, wo, proj);

    // LayerNorm + final PLIF -> d_out
    ln_plif<<<BN_, 256>>>(proj, gamma, beta, w_p, (float*)d_out);
}

// round 9
// speedup vs baseline: 1.1360x; 1.1360x over previous
#include <cuda_runtime.h>
#include <cstdint>
#include <math.h>

// Problem constants
#define T_    4
#define B_    32
#define N_    512
#define D_    256
#define H_    4
#define M_TOT (T_*B_*N_)          // 65536 rows
#define TPLANE (B_*N_*D_)         // 4194304 elements per timestep plane
#define PLANE (T_*TPLANE)         // 16777216 elements per full (T,B,N,D) tensor
#define BN_   (B_*N_)             // 16384
#define MASK_PER (T_*B_*N_*H_*2)  // 524288 uint32 words per spike tensor
#define FULLM 0xffffffffu

// ---------------------------------------------------------------------------
// Scratch (device globals; no cudaMalloc allowed)
// ---------------------------------------------------------------------------
__device__ float        g_y[3][PLANE];        // pre-activation q/k/v (192 MiB)
__device__ unsigned int g_masks[3][MASK_PER]; // q/k/v spike bitmasks (6 MiB)
__device__ float        g_attn[PLANE];        // attention output (t,b,n,D)
__device__ float        g_proj[PLANE];        // after wo projection

// ---------------------------------------------------------------------------
// Packed f32x2 helpers. fma.rn.f32x2: each 32-bit half is an IEEE-754 rn FMA,
// bit-identical to scalar fmaf. (SASS FFMA2; ptxas never auto-generates it.)
// ---------------------------------------------------------------------------
#define FMA2(d, a, b) asm("fma.rn.f32x2 %0, %1, %2, %0;" : "+l"(d) : "l"(a), "l"(b))

__device__ __forceinline__ unsigned long long dup2(float x) {
    unsigned long long r;
    unsigned int u = __float_as_uint(x);
    asm("mov.b64 %0, {%1, %1};" : "=l"(r) : "r"(u));
    return r;
}
__device__ __forceinline__ void unpack2(unsigned long long v, float& lo, float& hi) {
    unsigned int a, b;
    asm("mov.b64 {%0, %1}, %2;" : "=r"(a), "=r"(b) : "l"(v));
    lo = __uint_as_float(a); hi = __uint_as_float(b);
}

// ---------------------------------------------------------------------------
// SGEMM (NT) via packed FFMA2: C[M,256] = A[M,256] * W[256,256]^T, fp32.
// Per output element: pure ascending-k serial FMA chain — bit-identical to the
// scalar version (each f32x2 half is an independent IEEE-rn FMA).
// Block tile 128x256 (full N), 256 threads, 8x16 per-thread tile (64 f32x2
// accumulators). Double-buffered smem (exactly 48KB static).
// B stored in smem as float2 column pairs with XOR swizzle
//   S = (kc & 12) | (j & 3)  applied to the 16-wide column-group index,
// making both the transpose STS and the per-(kk,j) LDS.64 conflict-free.
// ---------------------------------------------------------------------------
__global__ __launch_bounds__(256, 1) void sgemm_f32x2(const float* __restrict__ A,
                                                      const float* __restrict__ W,
                                                      float* __restrict__ C) {
    __shared__ float As[2][16][128];               // [buf][kc][row]   (16KB)
    __shared__ unsigned long long Ws2[2][2048];    // [buf][(kc*8+j)*16 + c^S] (32KB)

    const int tid  = threadIdx.x;
    const int bm   = blockIdx.x * 128;
    const int trow = (tid >> 4) * 8;       // 0,8,..,120
    const int cgrp = tid & 15;             // column group: cols cgrp*16..+15
    const int lrow = tid >> 2;             // 0..63 (loader)
    const int lkc  = (tid & 3) * 4;        // 0,4,8,12 (loader k offset)

    unsigned long long acc[8][8];
#pragma unroll
    for (int i = 0; i < 8; i++)
#pragma unroll
        for (int j = 0; j < 8; j++) acc[i][j] = 0ull;

    float4 pa[2], pw[4];

    // ---- global prefetch of one k0 tile into registers ----
#define LOAD_GLOBAL(k0)  do {                                                        \
        pa[0] = *reinterpret_cast<const float4*>(&A[(size_t)(bm + lrow)      * 256 + (k0) + lkc]); \
        pa[1] = *reinterpret_cast<const float4*>(&A[(size_t)(bm + lrow + 64) * 256 + (k0) + lkc]); \
        pw[0] = *reinterpret_cast<const float4*>(&W[(size_t)(lrow)       * 256 + (k0) + lkc]);     \
        pw[1] = *reinterpret_cast<const float4*>(&W[(size_t)(lrow + 64)  * 256 + (k0) + lkc]);     \
        pw[2] = *reinterpret_cast<const float4*>(&W[(size_t)(lrow + 128) * 256 + (k0) + lkc]);     \
        pw[3] = *reinterpret_cast<const float4*>(&W[(size_t)(lrow + 192) * 256 + (k0) + lkc]);     \
    } while (0)

    // ---- scatter registers into smem (transposed, swizzled) ----
#define STORE_SMEM(buf)  do {                                                        \
        float av[2][4] = {{pa[0].x, pa[0].y, pa[0].z, pa[0].w},                      \
                          {pa[1].x, pa[1].y, pa[1].z, pa[1].w}};                     \
        _Pragma("unroll")                                                            \
        for (int l = 0; l < 2; l++) {                                                \
            int row = lrow + 64 * l;                                                 \
            _Pragma("unroll")                                                        \
            for (int ko = 0; ko < 4; ko++) As[buf][lkc + ko][row] = av[l][ko];       \
        }                                                                            \
        float* wf = reinterpret_cast<float*>(&Ws2[buf][0]);                          \
        float wv[4][4] = {{pw[0].x, pw[0].y, pw[0].z, pw[0].w},                      \
                          {pw[1].x, pw[1].y, pw[1].z, pw[1].w},                      \
                          {pw[2].x, pw[2].y, pw[2].z, pw[2].w},                      \
                          {pw[3].x, pw[3].y, pw[3].z, pw[3].w}};                     \
        _Pragma("unroll")                                                            \
        for (int l = 0; l < 4; l++) {                                                \
            int n  = lrow + 64 * l;                                                  \
            int cc = n >> 4, jj = (n & 15) >> 1, hf = n & 1;                         \
            _Pragma("unroll")                                                        \
            for (int ko = 0; ko < 4; ko++) {                                         \
                int kc = lkc + ko;                                                   \
                int sw = cc ^ ((kc & 12) | (jj & 3));                                \
                wf[(((kc * 8 + jj) * 16 + sw) << 1) + hf] = wv[l][ko];               \
            }                                                                        \
        }                                                                            \
    } while (0)

    LOAD_GLOBAL(0);
    STORE_SMEM(0);
    __syncthreads();

    int buf = 0;
    for (int k0 = 0; k0 < 256; k0 += 16) {
        const bool more = (k0 + 16 < 256);
        if (more) LOAD_GLOBAL(k0 + 16);

        // ---- compute 16 kk steps from smem[buf] ----
#pragma unroll
        for (int kk = 0; kk < 16; kk++) {
            float4 a0 = *reinterpret_cast<const float4*>(&As[buf][kk][trow]);
            float4 a1 = *reinterpret_cast<const float4*>(&As[buf][kk][trow + 4]);
            unsigned long long aa[8];
            aa[0] = dup2(a0.x); aa[1] = dup2(a0.y); aa[2] = dup2(a0.z); aa[3] = dup2(a0.w);
            aa[4] = dup2(a1.x); aa[5] = dup2(a1.y); aa[6] = dup2(a1.z); aa[7] = dup2(a1.w);

            unsigned long long bb[8];
#pragma unroll
            for (int j = 0; j < 8; j++) {
                int sw = cgrp ^ ((kk & 12) | (j & 3));
                bb[j] = Ws2[buf][(kk * 8 + j) * 16 + sw];
            }
#pragma unroll
            for (int i = 0; i < 8; i++)
#pragma unroll
                for (int j = 0; j < 8; j++) FMA2(acc[i][j], aa[i], bb[j]);
        }

        if (more) STORE_SMEM(buf ^ 1);
        __syncthreads();
        buf ^= 1;
    }

    // ---- epilogue: unpack and store ----
#pragma unroll
    for (int i = 0; i < 8; i++) {
        float* cp = &C[(size_t)(bm + trow + i) * 256 + cgrp * 16];
#pragma unroll
        for (int t4 = 0; t4 < 4; t4++) {
            float4 o;
            unpack2(acc[i][2 * t4],     o.x, o.y);
            unpack2(acc[i][2 * t4 + 1], o.z, o.w);
            *reinterpret_cast<float4*>(cp + 4 * t4) = o;
        }
    }
#undef LOAD_GLOBAL
#undef STORE_SMEM
}

// ---------------------------------------------------------------------------
// PLIF over T for q/k/v pre-activations -> spike bitmasks.
// decay = sigmoid(0) = exactly 0.5, so (x-v)*decay is EXACT; h has a single
// add rounding -> platform-independent. spike = (h >= 1).
// Mask layout: [((t*BN + bn)*H + h)*2 + word], word = (d>>5)&1, h = d>>6.
// ---------------------------------------------------------------------------
__global__ __launch_bounds__(256) void plif_spikes(const float* __restrict__ y,
                                                   const float* __restrict__ wp,
                                                   unsigned int* __restrict__ masks) {
    const int bn   = blockIdx.x;
    const int d    = threadIdx.x;
    const int lane = d & 31;
    const float decay = 1.f / (1.f + expf(-wp[0]));   // w=0 -> exactly 0.5
    const int idx0 = bn * 256 + d;
    float v = 0.f;
#pragma unroll
    for (int t = 0; t < 4; t++) {
        float u = y[(size_t)t * TPLANE + idx0];
        float h = __fadd_rn(v, __fmul_rn(__fsub_rn(u, v), decay));
        bool s = (h >= 1.0f);
        v = s ? 0.f : h;
        unsigned int bal = __ballot_sync(FULLM, s);
        if (lane == 0) {
            int hh   = d >> 6;
            int word = (d >> 5) & 1;
            masks[((t * BN_ + bn) * H_ + hh) * 2 + word] = bal;
        }
    }
}

// ---------------------------------------------------------------------------
// Fused attention per (t,b,h).  (UNCHANGED from R8 — bit-exact recipe)
// ---------------------------------------------------------------------------
__global__ __launch_bounds__(256) void attn_kernel(float* __restrict__ out) {
    const int tbh = blockIdx.x;
    const int h   = tbh & 3;
    const int tb  = tbh >> 2;              // t*32+b
    const int rowbase = blockIdx.y * 128;
    const int tid  = threadIdx.x;
    const int warp = tid >> 5;
    const int lane = tid & 31;

    __shared__ unsigned int klo[512], khi[512], vlo[512], vhi[512];
    __shared__ unsigned int vc[64][17];        // column-major v bits, padded
    __shared__ unsigned char dbuf[8][512];     // per-row (maxpc - pc) per m
    __shared__ float wtab[8][68];              // per-row 0.1*(LUT[d]/s)
    __shared__ float lut[65];                  // expf(-0.125*d)

    if (tid < 65) lut[tid] = expf(-0.125f * (float)tid);

    const unsigned int* qm = g_masks[0];
    const unsigned int* km = g_masks[1];
    const unsigned int* vm = g_masks[2];

    for (int n = tid; n < 512; n += 256) {
        int mi = ((tb * 512 + n) * 4 + h) * 2;
        klo[n] = km[mi]; khi[n] = km[mi + 1];
        vlo[n] = vm[mi]; vhi[n] = vm[mi + 1];
    }
    __syncthreads();

    // Transpose v bits into per-d columns via ballot
    for (int c = warp; c < 16; c += 8) {
        unsigned int wl = vlo[c * 32 + lane];
        unsigned int wh = vhi[c * 32 + lane];
#pragma unroll
        for (int dd = 0; dd < 32; dd++) {
            unsigned int b0 = __ballot_sync(FULLM, (wl >> dd) & 1u);
            unsigned int b1 = __ballot_sync(FULLM, (wh >> dd) & 1u);
            if (lane == dd) { vc[dd][c] = b0; vc[dd + 32][c] = b1; }
        }
    }
    __syncthreads();

    for (int it = 0; it < 16; it++) {
        int n  = rowbase + it * 8 + warp;
        int mi = ((tb * 512 + n) * 4 + h) * 2;
        unsigned int ql = qm[mi], qh = qm[mi + 1];

        // popcount logits (exact); row max (order-free on exact ints)
        int pc[16];
        int mx = 0;
#pragma unroll
        for (int j = 0; j < 16; j++) {
            int m = j * 32 + lane;
            pc[j] = __popc(ql & klo[m]) + __popc(qh & khi[m]);
            mx = max(mx, pc[j]);
        }
#pragma unroll
        for (int o = 16; o > 0; o >>= 1) mx = max(mx, __shfl_xor_sync(FULLM, mx, o));

        // exp values; per-simulated-warp shfl.down tree (XLA warp reduce)
        float p[16];
#pragma unroll
        for (int j = 0; j < 16; j++) {
            int dlt = mx - pc[j];
            dbuf[warp][j * 32 + lane] = (unsigned char)dlt;
            float v = lut[dlt];
            v = __fadd_rn(v, __shfl_down_sync(FULLM, v, 16));
            v = __fadd_rn(v, __shfl_down_sync(FULLM, v, 8));
            v = __fadd_rn(v, __shfl_down_sync(FULLM, v, 4));
            v = __fadd_rn(v, __shfl_down_sync(FULLM, v, 2));
            v = __fadd_rn(v, __shfl_down_sync(FULLM, v, 1));
            p[j] = __shfl_sync(FULLM, v, 0);   // warp-j partial, broadcast
        }
        // inter-warp combine: balanced down-tree over 16 partials (zero-padded
        // to 32 lanes in XLA -> offsets 16 add zeros exactly, then 8,4,2,1)
        float q0 = __fadd_rn(p[0], p[8]),  q1 = __fadd_rn(p[1], p[9]);
        float q2 = __fadd_rn(p[2], p[10]), q3 = __fadd_rn(p[3], p[11]);
        float q4 = __fadd_rn(p[4], p[12]), q5 = __fadd_rn(p[5], p[13]);
        float q6 = __fadd_rn(p[6], p[14]), q7 = __fadd_rn(p[7], p[15]);
        float r0 = __fadd_rn(q0, q4), r1 = __fadd_rn(q1, q5);
        float r2 = __fadd_rn(q2, q6), r3 = __fadd_rn(q3, q7);
        float s0 = __fadd_rn(r0, r2), s1 = __fadd_rn(r1, r3);
        float s  = __fadd_rn(s0, s1);

        // per-distinct-value attn_out = fl(0.1 * fl(e/s)) (reference order)
        for (int d = lane; d < 65; d += 32)
            wtab[warp][d] = __fmul_rn(0.1f, __fdiv_rn(lut[d], s));
        __syncwarp();

        // sparse attn @ v: ascending walk == serial ascending-m FMA
        float acc0 = 0.f, acc1 = 0.f;
        const int d0 = lane, d1 = lane + 32;
#pragma unroll 4
        for (int c = 0; c < 16; c++) {
            unsigned int w0 = vc[d0][c];
            unsigned int w1 = vc[d1][c];
            const unsigned char* db = &dbuf[warp][c * 32];
            while (w0) { int j = __ffs(w0) - 1; w0 &= w0 - 1; acc0 = __fadd_rn(acc0, wtab[warp][db[j]]); }
            while (w1) { int j = __ffs(w1) - 1; w1 &= w1 - 1; acc1 = __fadd_rn(acc1, wtab[warp][db[j]]); }
        }
        int ob = (tb * 512 + n) * 256 + h * 64;
        out[ob + d0] = acc0;
        out[ob + d1] = acc1;
        __syncwarp();
    }
}

// ---------------------------------------------------------------------------
// LayerNorm over D then final PLIF over T. (UNCHANGED from R8 — bit-exact)
// ---------------------------------------------------------------------------
__global__ __launch_bounds__(256) void ln_plif(const float* __restrict__ X,
                                               const float* __restrict__ gamma,
                                               const float* __restrict__ beta,
                                               const float* __restrict__ wp,
                                               float* __restrict__ out) {
    const int bn   = blockIdx.x;
    const int d    = threadIdx.x;
    const int lane = d & 31, warp = d >> 5;
    __shared__ float part[8];
    __shared__ float bcast;
    const float decay = 1.f / (1.f + expf(-wp[0]));   // exactly 0.5
    const float g  = gamma[d];
    const float be = beta[d];
    float v = 0.f;

#pragma unroll
    for (int t = 0; t < 4; t++) {
        float x = X[(size_t)t * TPLANE + (size_t)bn * 256 + d];

        // ---- mean: warp down-tree, then padded down-tree over 8 partials ----
        float sv = x;
        sv = __fadd_rn(sv, __shfl_down_sync(FULLM, sv, 16));
        sv = __fadd_rn(sv, __shfl_down_sync(FULLM, sv, 8));
        sv = __fadd_rn(sv, __shfl_down_sync(FULLM, sv, 4));
        sv = __fadd_rn(sv, __shfl_down_sync(FULLM, sv, 2));
        sv = __fadd_rn(sv, __shfl_down_sync(FULLM, sv, 1));
        if (lane == 0) part[warp] = sv;
        __syncthreads();
        if (warp == 0) {
            float pv = (lane < 8) ? part[lane] : 0.f;
            pv = __fadd_rn(pv, __shfl_down_sync(FULLM, pv, 16));  // +0 exact
            pv = __fadd_rn(pv, __shfl_down_sync(FULLM, pv, 8));   // +0 exact
            pv = __fadd_rn(pv, __shfl_down_sync(FULLM, pv, 4));
            pv = __fadd_rn(pv, __shfl_down_sync(FULLM, pv, 2));
            pv = __fadd_rn(pv, __shfl_down_sync(FULLM, pv, 1));
            if (lane == 0) bcast = __fmul_rn(pv, (1.f / 256.f));  // exact pow2
        }
        __syncthreads();
        float mu = bcast;
        __syncthreads();

        // ---- variance: same association over centered squares ----
        float c  = __fsub_rn(x, mu);
        float qv = __fmul_rn(c, c);
        qv = __fadd_rn(qv, __shfl_down_sync(FULLM, qv, 16));
        qv = __fadd_rn(qv, __shfl_down_sync(FULLM, qv, 8));
        qv = __fadd_rn(qv, __shfl_down_sync(FULLM, qv, 4));
        qv = __fadd_rn(qv, __shfl_down_sync(FULLM, qv, 2));
        qv = __fadd_rn(qv, __shfl_down_sync(FULLM, qv, 1));
        if (lane == 0) part[warp] = qv;
        __syncthreads();
        if (warp == 0) {
            float pv = (lane < 8) ? part[lane] : 0.f;
            pv = __fadd_rn(pv, __shfl_down_sync(FULLM, pv, 16));
            pv = __fadd_rn(pv, __shfl_down_sync(FULLM, pv, 8));
            pv = __fadd_rn(pv, __shfl_down_sync(FULLM, pv, 4));
            pv = __fadd_rn(pv, __shfl_down_sync(FULLM, pv, 2));
            pv = __fadd_rn(pv, __shfl_down_sync(FULLM, pv, 1));
            if (lane == 0) bcast = __fmul_rn(pv, (1.f / 256.f));
        }
        __syncthreads();
        float var = bcast;
        __syncthreads();

        float rs = rsqrtf(__fadd_rn(var, 1e-5f));
        float y  = __fadd_rn(__fmul_rn(__fmul_rn(c, rs), g), be);
        float hh = __fadd_rn(v, __fmul_rn(__fsub_rn(y, v), decay));
        bool sp = (hh >= 1.0f);
        out[(size_t)t * TPLANE + (size_t)bn * 256 + d] = sp ? 1.f : 0.f;
        v = sp ? 0.f : hh;
    }
}

// ---------------------------------------------------------------------------
extern "C" void kernel_launch(void* const* d_in, const int* in_sizes, int n_in,
                              void* d_out, int out_size) {
    const float* x     = (const float*)d_in[0];
    const float* wq    = (const float*)d_in[1];
    const float* wk    = (const float*)d_in[2];
    const float* wv    = (const float*)d_in[3];
    const float* wo    = (const float*)d_in[4];
    const float* gamma = (const float*)d_in[5];
    const float* beta  = (const float*)d_in[6];
    const float* w_q   = (const float*)d_in[7];
    const float* w_k   = (const float*)d_in[8];
    const float* w_v   = (const float*)d_in[9];
    // d_in[10] = w_attn: unused — attn PLIF provably never spikes (softmax < V_TH)
    const float* w_p   = (const float*)d_in[11];

    float* y;  float* attn;  float* proj;  unsigned int* masks;
    cudaGetSymbolAddress((void**)&y,     g_y);
    cudaGetSymbolAddress((void**)&masks, g_masks);
    cudaGetSymbolAddress((void**)&attn,  g_attn);
    cudaGetSymbolAddress((void**)&proj,  g_proj);

    // q/k/v pre-activation GEMMs (FFMA2, bit-identical rounding to R8)
    sgemm_f32x2<<<M_TOT / 128, 256>>>(x, wq, y);
    sgemm_f32x2<<<M_TOT / 128, 256>>>(x, wk, y + (size_t)PLANE);
    sgemm_f32x2<<<M_TOT / 128, 256>>>(x, wv, y + (size_t)2 * PLANE);

    // PLIF -> spike bitmasks
    plif_spikes<<<BN_, 256>>>(y,                    w_q, masks);
    plif_spikes<<<BN_, 256>>>(y + (size_t)PLANE,    w_k, masks + MASK_PER);
    plif_spikes<<<BN_, 256>>>(y + (size_t)2*PLANE,  w_v, masks + 2 * MASK_PER);

    // fused attention (popcount logits + XLA-tree softmax + sparse AV)
    attn_kernel<<<dim3(T_ * B_ * H_, 4), 256>>>(attn);

    // output projection
    sgemm_f32x2<<<M_TOT / 128, 256>>>(attn, wo, proj);

    // LayerNorm + final PLIF -> d_out
    ln_plif<<<BN_, 256>>>(proj, gamma, beta, w_p, (float*)d_out);
}